// round 8
// baseline (speedup 1.0000x reference)
#include <cuda_runtime.h>
#include <cfloat>
#include <math.h>

#define NPIL 30000
#define MPTS 32
#define NMTOT (30000.0 * 32.0)
#define LOG2E 1.4426950408889634f

// ---------------- scratch (device globals; zero-initialized at load) ----------------
__device__ float    g_w[NPIL * MPTS];   // per-point attention weight
__device__ float4   g_pmean[NPIL];      // per-pillar xyz mean (w stays 0)
__device__ float2   g_wmm[NPIL];        // (max,min) of w over MASKED lanes
__device__ double   g_mom[65];          // BN sufficient statistics (re-zeroed by k_stats)
__device__ float    g_As[64 * 4];       // [c][4]  A_c * s_c
__device__ float    g_Gs[6 * 64];       // [a][c]  G_c * s_c  (channel-contiguous)
__device__ float    g_t[64];            // t_c = beta - mean*s

// QQ triangular index tables (l-38 -> (a,b))
__constant__ signed char d_qa[21] = {0,0,0,0,0,0,1,1,1,1,1,2,2,2,2,3,3,3,4,4,5};
__constant__ signed char d_qb[21] = {0,1,2,3,4,5,1,2,3,4,5,2,3,4,5,3,4,5,4,5,5};

__device__ __forceinline__ float ex2f(float x) {
    float y; asm("ex2.approx.f32 %0, %1;" : "=f"(y) : "f"(x)); return y;
}
__device__ __forceinline__ float wredsum(float v) {
#pragma unroll
    for (int o = 16; o; o >>= 1) v += __shfl_xor_sync(0xffffffffu, v, o);
    return v;
}
__device__ __forceinline__ float wredmax(float v) {
#pragma unroll
    for (int o = 16; o; o >>= 1) v = fmaxf(v, __shfl_xor_sync(0xffffffffu, v, o));
    return v;
}
__device__ __forceinline__ float wredmin(float v) {
#pragma unroll
    for (int o = 16; o; o >>= 1) v = fminf(v, __shfl_xor_sync(0xffffffffu, v, o));
    return v;
}

// moment-tail: value for red slot l (14..64) from per-pillar scalars
// sqw[0..5] = q6, sqw[6..9] = Sv
__device__ __forceinline__ float tail_val(int l, const float* sqw, float fm) {
    if (l < 38) { int u = l - 14; return sqw[u >> 2] * sqw[6 + (u & 3)]; }
    if (l < 59) { int u = l - 38; return fm * sqw[(int)d_qa[u]] * sqw[(int)d_qb[u]]; }
    return fm * sqw[l - 59];
}

// ---------------- pass 1: attention + distributed moment accumulation ----------------
__global__ __launch_bounds__(256) void k_pass1(
    const float4* __restrict__ feat, const int* __restrict__ npts,
    const int4*  __restrict__ coors,
    const float* __restrict__ wq, const float* __restrict__ wk,
    const float* __restrict__ wv, const float* __restrict__ wo,
    const float* __restrict__ bq, const float* __restrict__ bk,
    const float* __restrict__ bv, const float* __restrict__ bo)
{
    __shared__ float kvs[8][32][8];   // k0*log2e,k1*log2e,k2*log2e,v0,v1,v2,pad,pad
    __shared__ float red[8][65];
    __shared__ float sq[8][10];       // [0..5]=q6, [6..9]=Sv
    __shared__ float swt[48];         // wq9 wk9 wv9 wo9 bq3 bk3 bv3 bo3
    const int tid  = threadIdx.x;
    const int wl   = tid >> 5;
    const int lane = tid & 31;
    const int n    = blockIdx.x * 8 + wl;

    {   // stage small weights into smem
        int t = tid;
        if      (t <  9) swt[t] = wq[t];
        else if (t < 18) swt[t] = wk[t - 9];
        else if (t < 27) swt[t] = wv[t - 18];
        else if (t < 36) swt[t] = wo[t - 27];
        else if (t < 39) swt[t] = bq[t - 36];
        else if (t < 42) swt[t] = bk[t - 39];
        else if (t < 45) swt[t] = bv[t - 42];
        else if (t < 48) swt[t] = bo[t - 45];
    }
    __syncthreads();

    float4 f = feat[n * MPTS + lane];
    const float x = f.x, y = f.y, z = f.z, I = f.w;

    {   // ---- attention ----
        float q0 = fmaf(x, swt[0], fmaf(y, swt[3], fmaf(z, swt[6], swt[36])));
        float q1 = fmaf(x, swt[1], fmaf(y, swt[4], fmaf(z, swt[7], swt[37])));
        float q2 = fmaf(x, swt[2], fmaf(y, swt[5], fmaf(z, swt[8], swt[38])));
        float k0 = fmaf(x, swt[ 9], fmaf(y, swt[12], fmaf(z, swt[15], swt[39])));
        float k1 = fmaf(x, swt[10], fmaf(y, swt[13], fmaf(z, swt[16], swt[40])));
        float k2 = fmaf(x, swt[11], fmaf(y, swt[14], fmaf(z, swt[17], swt[41])));
        float v0 = fmaf(x, swt[18], fmaf(y, swt[21], fmaf(z, swt[24], swt[42])));
        float v1 = fmaf(x, swt[19], fmaf(y, swt[22], fmaf(z, swt[25], swt[43])));
        float v2 = fmaf(x, swt[20], fmaf(y, swt[23], fmaf(z, swt[26], swt[44])));

        float* kp = kvs[wl][lane];
        *(float4*)kp       = make_float4(k0 * LOG2E, k1 * LOG2E, k2 * LOG2E, v0);
        *(float2*)(kp + 4) = make_float2(v1, v2);
        __syncwarp();

        float n0 = 0.f, n1 = 0.f, n2 = 0.f, d0 = 0.f, d1 = 0.f, d2 = 0.f;
#pragma unroll
        for (int j = 0; j < 32; j++) {
            const float* kj = kvs[wl][j];
            float4 a = *(const float4*)kj;
            float2 b = *(const float2*)(kj + 4);
            float e0 = ex2f(q0 * a.x);
            float e1 = ex2f(q1 * a.y);
            float e2 = ex2f(q2 * a.z);
            n0 = fmaf(e0, a.w, n0); d0 += e0;
            n1 = fmaf(e1, b.x, n1); d1 += e1;
            n2 = fmaf(e2, b.y, n2); d2 += e2;
        }
        float o0 = __fdividef(n0, d0);
        float o1 = __fdividef(n1, d1);
        float o2 = __fdividef(n2, d2);

        float a0 = fmaf(o0, swt[27], fmaf(o1, swt[30], fmaf(o2, swt[33], swt[45])));
        float a1 = fmaf(o0, swt[28], fmaf(o1, swt[31], fmaf(o2, swt[34], swt[46])));
        float a2 = fmaf(o0, swt[29], fmaf(o1, swt[32], fmaf(o2, swt[35], swt[47])));
        float matt = fmaxf(a0, fmaxf(a1, a2));

        float ssum = wredsum(matt);
        float wgt = matt / ssum;        // IEEE div: ssum may cancel
        g_w[n * MPTS + lane] = wgt;

        const int m = npts[n];
        const float fm = (float)m;
        const float inv_m = 1.0f / fm;
        const bool act = lane < m;

        // masked max/min of w (for pass2 closed form)
        float wmx = wredmax(act ? -FLT_MAX : wgt);
        float wmn = wredmin(act ?  FLT_MAX : wgt);
        if (lane == 0) g_wmm[n] = make_float2(wmx, wmn);

        // ---- 16-value reduce-scatter: V[0..13]=masked moments, V[14]=x, V[15]=y ----
        float px = act ? x : 0.f, py = act ? y : 0.f;
        float pz = act ? z : 0.f, pI = act ? I : 0.f;
        float V[16] = { px*px, px*py, px*pz, px*pI, py*py, py*pz, py*pI,
                        pz*pz, pz*pI, pI*pI, px, py, pz, pI, x, y };

#pragma unroll
        for (int t = 0; t < 16; t++)
            V[t] += __shfl_xor_sync(0xffffffffu, V[t], 16);   // both halves valid

        float W8[8];
#pragma unroll
        for (int t = 0; t < 8; t++) {
            bool hi = (lane & 8);
            float snd = hi ? V[t] : V[t + 8];
            float kp2 = hi ? V[t + 8] : V[t];
            W8[t] = kp2 + __shfl_xor_sync(0xffffffffu, snd, 8);
        }
        float W4[4];
#pragma unroll
        for (int t = 0; t < 4; t++) {
            bool hi = (lane & 4);
            float snd = hi ? W8[t] : W8[t + 4];
            float kp2 = hi ? W8[t + 4] : W8[t];
            W4[t] = kp2 + __shfl_xor_sync(0xffffffffu, snd, 4);
        }
        float W2[2];
#pragma unroll
        for (int t = 0; t < 2; t++) {
            bool hi = (lane & 2);
            float snd = hi ? W2[0] * 0.f + (hi ? W4[t] : W4[t + 2]) : W4[t + 2];
            // (see below: simplified rewrite)
            snd = hi ? W4[t] : W4[t + 2];
            float kp2 = hi ? W4[t + 2] : W4[t];
            W2[t] = kp2 + __shfl_xor_sync(0xffffffffu, snd, 2);
        }
        float fin;
        {
            bool hi = (lane & 1);
            float snd = hi ? W2[0] : W2[1];
            float kp2 = hi ? W2[1] : W2[0];
            fin = kp2 + __shfl_xor_sync(0xffffffffu, snd, 1);
        }
        // lane l holds total of V[l & 15]

        // z sum (unmasked) separately: allreduce
        float sz = wredsum(z);

        // scatter per-pillar scalars into smem / red / pmean
        if (lane < 14) red[wl][lane] = fin;                 // PP(10) + Sv(4)
        if (lane >= 26 && lane < 30) sq[wl][lane - 20] = fin; // Sv dup -> sq[6..9]
        if (lane == 14) { float mv = fin * inv_m; sq[wl][3] = mv; g_pmean[n].x = mv; }
        if (lane == 15) { float mv = fin * inv_m; sq[wl][4] = mv; g_pmean[n].y = mv; }
        if (lane == 16) { float mv = sz  * inv_m; sq[wl][5] = mv; g_pmean[n].z = mv; }

        int4 cc = coors[n];                                 // uniform LDG (all lanes)
        float cxv = fmaf((float)cc.w, 0.2f, 0.1f);
        float cyv = fmaf((float)cc.z, 0.2f, -39.9f);
        float czv = fmaf((float)cc.y, 4.0f, -1.0f);
        if (lane == 0) sq[wl][0] = cxv;
        if (lane == 1) sq[wl][1] = cyv;
        if (lane == 2) sq[wl][2] = czv;
        __syncwarp();

        // distributed moment tail: lanes compute red[14..64]
        const float* sqw = sq[wl];
        {
            int l1 = 14 + lane;                 // 14..45
            red[wl][l1] = tail_val(l1, sqw, fm);
            if (lane < 19) {
                int l2 = 46 + lane;             // 46..64
                red[wl][l2] = tail_val(l2, sqw, fm);
            }
        }
    }
    __syncthreads();
    if (tid < 65) {
        double acc = 0.0;
#pragma unroll
        for (int w2 = 0; w2 < 8; w2++) acc += (double)red[w2][tid];
        atomicAdd(&g_mom[tid], acc);
    }
}

// ---------------- stats: fold BN into per-channel coefficients; self-reset g_mom ----------------
__global__ void k_stats(const float* __restrict__ pfn_w,
                        const float* __restrict__ gamma,
                        const float* __restrict__ beta)
{
    const int tid = threadIdx.x;
    if (tid < 64) {
        const int c = tid;
        float W[10];
#pragma unroll
        for (int r = 0; r < 10; r++) W[r] = pfn_w[r * 64 + c];
        float A[4] = { W[0]+W[4]+W[7], W[1]+W[5]+W[8], W[2]+W[6]+W[9], W[3] };
        float G[6] = { -(W[0]+W[7]), -(W[1]+W[8]), -(W[2]+W[9]), -W[4], -W[5], -W[6] };

        double mom[65];
        for (int t = 0; t < 65; t++) mom[t] = g_mom[t];

        double S1 = 0.0;
#pragma unroll
        for (int d = 0; d < 4; d++) S1 += mom[10 + d] * (double)A[d];
#pragma unroll
        for (int a = 0; a < 6; a++) S1 += mom[59 + a] * (double)G[a];
        double mean = S1 / NMTOT;

        double E2 = 0.0;
        int pi = 0;
#pragma unroll
        for (int d = 0; d < 4; d++)
#pragma unroll
            for (int e = d; e < 4; e++)
                E2 += (d == e ? 1.0 : 2.0) * (double)A[d] * (double)A[e] * mom[pi++];
#pragma unroll
        for (int a = 0; a < 6; a++)
#pragma unroll
            for (int d = 0; d < 4; d++)
                E2 += 2.0 * (double)G[a] * (double)A[d] * mom[14 + a * 4 + d];
        int qi = 38;
#pragma unroll
        for (int a = 0; a < 6; a++)
#pragma unroll
            for (int b = a; b < 6; b++)
                E2 += (a == b ? 1.0 : 2.0) * (double)G[a] * (double)G[b] * mom[qi++];
        E2 /= NMTOT;

        double var = E2 - mean * mean;
        float s = gamma[c] * (float)(1.0 / sqrt(var + 1e-3));
        float t = beta[c] - (float)mean * s;
#pragma unroll
        for (int d = 0; d < 4; d++) g_As[c * 4 + d] = A[d] * s;
#pragma unroll
        for (int a = 0; a < 6; a++) g_Gs[a * 64 + c] = G[a] * s;
        g_t[c] = t;
    }
    __syncthreads();                    // all reads of g_mom complete
    if (tid < 65) g_mom[tid] = 0.0;     // reset for next graph replay
}

// ---------------- pass 2: fused PFN + BN + leaky + fa/fm (high occupancy, lean) ----------------
__global__ __launch_bounds__(256, 5) void k_pass2(
    const float4* __restrict__ feat, const int* __restrict__ npts,
    const int4*  __restrict__ coors, float* __restrict__ out)
{
    __shared__ float4 sp[8][32];
    __shared__ float  sw[8][32];
    const int lane = threadIdx.x & 31;
    const int wl = threadIdx.x >> 5;
    const int gw = blockIdx.x * 8 + wl;
    const int nw = gridDim.x * 8;

    // coefficients for channel pair (2*lane, 2*lane+1)
    const float4* A4 = (const float4*)g_As;
    float4 Aa = A4[2 * lane];
    float4 Ab = A4[2 * lane + 1];
    float2 Gv[6];
#pragma unroll
    for (int a = 0; a < 6; a++) Gv[a] = ((const float2*)(g_Gs + 64 * a))[lane];
    float2 tv = ((const float2*)g_t)[lane];
    const float tp0 = fmaxf(tv.x, 0.01f * tv.x);
    const float tp1 = fmaxf(tv.y, 0.01f * tv.y);

    for (int n = gw; n < NPIL; n += nw) {
        float4 f  = feat[n * MPTS + lane];
        float  wv = g_w[n * MPTS + lane];
        const int m = npts[n];
        int4 cc = coors[n];
        float4 pmv = g_pmean[n];
        float2 wmm = g_wmm[n];
        sp[wl][lane] = f;
        sw[wl][lane] = wv;
        __syncwarp();

        float k0 = tv.x, k1 = tv.y;
        {
            float q0 = fmaf((float)cc.w, 0.2f, 0.1f);
            float q1 = fmaf((float)cc.z, 0.2f, -39.9f);
            float q2 = fmaf((float)cc.y, 4.0f, -1.0f);
            k0 = fmaf(q0, Gv[0].x, fmaf(q1, Gv[1].x, fmaf(q2, Gv[2].x,
                 fmaf(pmv.x, Gv[3].x, fmaf(pmv.y, Gv[4].x, fmaf(pmv.z, Gv[5].x, k0))))));
            k1 = fmaf(q0, Gv[0].y, fmaf(q1, Gv[1].y, fmaf(q2, Gv[2].y,
                 fmaf(pmv.x, Gv[3].y, fmaf(pmv.y, Gv[4].y, fmaf(pmv.z, Gv[5].y, k1))))));
        }

        float fm0, fm1, fa0, fa1;
        if (m < MPTS) {                  // masked rows contribute x = t_c
            fm0 = tp0; fm1 = tp1;
            fa0 = (tp0 >= 0.f) ? tp0 * wmm.x : tp0 * wmm.y;
            fa1 = (tp1 >= 0.f) ? tp1 * wmm.x : tp1 * wmm.y;
        } else {
            fm0 = fm1 = fa0 = fa1 = -FLT_MAX;
        }

#pragma unroll 4
        for (int i = 0; i < m; i++) {
            float4 p = sp[wl][i];
            float wi = sw[wl][i];
            float r0 = fmaf(p.x, Aa.x, fmaf(p.y, Aa.y,
                       fmaf(p.z, Aa.z, fmaf(p.w, Aa.w, k0))));
            float u0 = fmaxf(r0, 0.01f * r0);
            fm0 = fmaxf(fm0, u0);
            fa0 = fmaxf(fa0, wi * u0);
            float r1 = fmaf(p.x, Ab.x, fmaf(p.y, Ab.y,
                       fmaf(p.z, Ab.z, fmaf(p.w, Ab.w, k1))));
            float u1 = fmaxf(r1, 0.01f * r1);
            fm1 = fmaxf(fm1, u1);
            fa1 = fmaxf(fa1, wi * u1);
        }
        ((float2*)(out + n * 64))[lane] =
            make_float2(0.5f * (fa0 + fm0), 0.5f * (fa1 + fm1));
        __syncwarp();
    }
}

// ---------------- launch ----------------
extern "C" void kernel_launch(void* const* d_in, const int* in_sizes, int n_in,
                              void* d_out, int out_size)
{
    const float4* feat  = (const float4*)d_in[0];
    const int*    npts  = (const int*)  d_in[1];
    const int4*   coors = (const int4*) d_in[2];
    const float*  pfn_w = (const float*)d_in[3];
    const float*  gamma = (const float*)d_in[4];
    const float*  beta  = (const float*)d_in[5];
    const float*  wq    = (const float*)d_in[6];
    const float*  wk    = (const float*)d_in[7];
    const float*  wv    = (const float*)d_in[8];
    const float*  wo    = (const float*)d_in[9];
    const float*  bq    = (const float*)d_in[10];
    const float*  bk    = (const float*)d_in[11];
    const float*  bv    = (const float*)d_in[12];
    const float*  bo    = (const float*)d_in[13];
    float* out = (float*)d_out;

    k_pass1<<<(NPIL + 7) / 8, 256>>>(feat, npts, coors, wq, wk, wv, wo,
                                     bq, bk, bv, bo);
    k_stats<<<1, 128>>>(pfn_w, gamma, beta);
    k_pass2<<<740, 256>>>(feat, npts, coors, out);
}

// round 11
// speedup vs baseline: 1.0275x; 1.0275x over previous
#include <cuda_runtime.h>
#include <cfloat>
#include <math.h>

#define NPIL 30000
#define HALFP 15000
#define MPTS 32
#define NMTOT (30000.0f * 32.0f)
#define LOG2E 1.4426950408889634f

// ---------------- scratch (device globals; zero-initialized at load) ----------------
__device__ float    g_w[NPIL * MPTS];   // per-point attention weight
__device__ float4   g_pmean[NPIL];      // per-pillar xyz mean (w stays 0)
__device__ float2   g_wmm[NPIL];        // (max,min) of w over MASKED lanes
__device__ double   g_mom[65];          // BN sufficient statistics (reset by pass2 last block)
__device__ unsigned g_ctr2;             // pass2 completion ticket

// QQ triangular index tables (l-38 -> (a,b))
__constant__ signed char d_qa[21] = {0,0,0,0,0,0,1,1,1,1,1,2,2,2,2,3,3,3,4,4,5};
__constant__ signed char d_qb[21] = {0,1,2,3,4,5,1,2,3,4,5,2,3,4,5,3,4,5,4,5,5};

__device__ __forceinline__ float ex2f(float x) {
    float y; asm("ex2.approx.f32 %0, %1;" : "=f"(y) : "f"(x)); return y;
}
__device__ __forceinline__ float wredsum(float v) {
#pragma unroll
    for (int o = 16; o; o >>= 1) v += __shfl_xor_sync(0xffffffffu, v, o);
    return v;
}
__device__ __forceinline__ float wredmax(float v) {
#pragma unroll
    for (int o = 16; o; o >>= 1) v = fmaxf(v, __shfl_xor_sync(0xffffffffu, v, o));
    return v;
}
__device__ __forceinline__ float wredmin(float v) {
#pragma unroll
    for (int o = 16; o; o >>= 1) v = fminf(v, __shfl_xor_sync(0xffffffffu, v, o));
    return v;
}

// moment-tail: value for red slot l (14..64) from per-pillar scalars
// sqw[0..5] = q6, sqw[6..9] = Sv
__device__ __forceinline__ float tail_val(int l, const float* sqw, float fm) {
    if (l < 38) { int u = l - 14; return sqw[u >> 2] * sqw[6 + (u & 3)]; }
    if (l < 59) { int u = l - 38; return fm * sqw[(int)d_qa[u]] * sqw[(int)d_qb[u]]; }
    return fm * sqw[l - 59];
}

// ---------------- pass 1: attention + moments, 2 pillars per warp ----------------
__global__ __launch_bounds__(256) void k_pass1(
    const float4* __restrict__ feat, const int* __restrict__ npts,
    const int4*  __restrict__ coors,
    const float* __restrict__ wq, const float* __restrict__ wk,
    const float* __restrict__ wv, const float* __restrict__ wo,
    const float* __restrict__ bq, const float* __restrict__ bk,
    const float* __restrict__ bv, const float* __restrict__ bo)
{
    __shared__ __align__(16) float kvs[8][32][8]; // k*log2e x3, v x3, pad x2
    __shared__ float red[8][65];
    __shared__ float sq[8][10];       // [0..5]=q6, [6..9]=Sv
    __shared__ float swt[48];         // wq9 wk9 wv9 wo9 bq3 bk3 bv3 bo3
    const int tid  = threadIdx.x;
    const int wl   = tid >> 5;
    const int lane = tid & 31;
    const int n0   = blockIdx.x * 8 + wl;

    {   // stage small weights into smem
        int t = tid;
        if      (t <  9) swt[t] = wq[t];
        else if (t < 18) swt[t] = wk[t - 9];
        else if (t < 27) swt[t] = wv[t - 18];
        else if (t < 36) swt[t] = wo[t - 27];
        else if (t < 39) swt[t] = bq[t - 36];
        else if (t < 42) swt[t] = bk[t - 39];
        else if (t < 45) swt[t] = bv[t - 42];
        else if (t < 48) swt[t] = bo[t - 45];
    }
    __syncthreads();

    // per-lane moment accumulators across the 2 pillars
    float a0 = 0.f, a1 = 0.f, a2 = 0.f;

#pragma unroll 1
    for (int rep = 0; rep < 2; rep++) {
        const int n = n0 + rep * HALFP;
        float4 f = feat[n * MPTS + lane];
        const float x = f.x, y = f.y, z = f.z, I = f.w;

        // ---- attention ----
        float q0 = fmaf(x, swt[0], fmaf(y, swt[3], fmaf(z, swt[6], swt[36])));
        float q1 = fmaf(x, swt[1], fmaf(y, swt[4], fmaf(z, swt[7], swt[37])));
        float q2 = fmaf(x, swt[2], fmaf(y, swt[5], fmaf(z, swt[8], swt[38])));
        float k0 = fmaf(x, swt[ 9], fmaf(y, swt[12], fmaf(z, swt[15], swt[39])));
        float k1 = fmaf(x, swt[10], fmaf(y, swt[13], fmaf(z, swt[16], swt[40])));
        float k2 = fmaf(x, swt[11], fmaf(y, swt[14], fmaf(z, swt[17], swt[41])));
        float v0 = fmaf(x, swt[18], fmaf(y, swt[21], fmaf(z, swt[24], swt[42])));
        float v1 = fmaf(x, swt[19], fmaf(y, swt[22], fmaf(z, swt[25], swt[43])));
        float v2 = fmaf(x, swt[20], fmaf(y, swt[23], fmaf(z, swt[26], swt[44])));

        float* kp = kvs[wl][lane];
        *(float4*)kp       = make_float4(k0 * LOG2E, k1 * LOG2E, k2 * LOG2E, v0);
        *(float2*)(kp + 4) = make_float2(v1, v2);
        __syncwarp();

        float n0a = 0.f, n1a = 0.f, n2a = 0.f, d0 = 0.f, d1 = 0.f, d2 = 0.f;
#pragma unroll
        for (int j = 0; j < 32; j++) {
            const float* kj = kvs[wl][j];
            float4 a = *(const float4*)kj;
            float2 b = *(const float2*)(kj + 4);
            float e0 = ex2f(q0 * a.x);
            float e1 = ex2f(q1 * a.y);
            float e2 = ex2f(q2 * a.z);
            n0a = fmaf(e0, a.w, n0a); d0 += e0;
            n1a = fmaf(e1, b.x, n1a); d1 += e1;
            n2a = fmaf(e2, b.y, n2a); d2 += e2;
        }
        float o0 = __fdividef(n0a, d0);
        float o1 = __fdividef(n1a, d1);
        float o2 = __fdividef(n2a, d2);

        float b0 = fmaf(o0, swt[27], fmaf(o1, swt[30], fmaf(o2, swt[33], swt[45])));
        float b1 = fmaf(o0, swt[28], fmaf(o1, swt[31], fmaf(o2, swt[34], swt[46])));
        float b2 = fmaf(o0, swt[29], fmaf(o1, swt[32], fmaf(o2, swt[35], swt[47])));
        float matt = fmaxf(b0, fmaxf(b1, b2));

        float ssum = wredsum(matt);
        float wgt = matt / ssum;        // IEEE div: ssum may cancel
        g_w[n * MPTS + lane] = wgt;

        const int m = npts[n];
        const float fm = (float)m;
        const float inv_m = 1.0f / fm;
        const bool act = lane < m;

        // masked max/min of w (for pass2 closed form)
        float wmx = wredmax(act ? -FLT_MAX : wgt);
        float wmn = wredmin(act ?  FLT_MAX : wgt);
        if (lane == 0) g_wmm[n] = make_float2(wmx, wmn);

        // ---- 16-value reduce-scatter: V[0..13]=masked moments, V[14]=x, V[15]=y ----
        float px = act ? x : 0.f, py = act ? y : 0.f;
        float pz = act ? z : 0.f, pI = act ? I : 0.f;
        float V[16] = { px*px, px*py, px*pz, px*pI, py*py, py*pz, py*pI,
                        pz*pz, pz*pI, pI*pI, px, py, pz, pI, x, y };

#pragma unroll
        for (int t = 0; t < 16; t++)
            V[t] += __shfl_xor_sync(0xffffffffu, V[t], 16);

        float W8[8];
#pragma unroll
        for (int t = 0; t < 8; t++) {
            bool hi = (lane & 8);
            float snd = hi ? V[t] : V[t + 8];
            float kp2 = hi ? V[t + 8] : V[t];
            W8[t] = kp2 + __shfl_xor_sync(0xffffffffu, snd, 8);
        }
        float W4[4];
#pragma unroll
        for (int t = 0; t < 4; t++) {
            bool hi = (lane & 4);
            float snd = hi ? W8[t] : W8[t + 4];
            float kp2 = hi ? W8[t + 4] : W8[t];
            W4[t] = kp2 + __shfl_xor_sync(0xffffffffu, snd, 4);
        }
        float W2[2];
#pragma unroll
        for (int t = 0; t < 2; t++) {
            bool hi = (lane & 2);
            float snd = hi ? W4[t] : W4[t + 2];
            float kp2 = hi ? W4[t + 2] : W4[t];
            W2[t] = kp2 + __shfl_xor_sync(0xffffffffu, snd, 2);
        }
        float fin;
        {
            bool hi = (lane & 1);
            float snd = hi ? W2[0] : W2[1];
            float kp2 = hi ? W2[1] : W2[0];
            fin = kp2 + __shfl_xor_sync(0xffffffffu, snd, 1);
        }
        // lane l holds total of V[l & 15]

        float sz = wredsum(z);          // unmasked z sum

        // scatter per-pillar scalars into smem / pmean
        if (lane >= 26 && lane < 30) sq[wl][lane - 20] = fin;   // Sv dup -> sq[6..9]
        if (lane == 14) { float mv = fin * inv_m; sq[wl][3] = mv; g_pmean[n].x = mv; }
        if (lane == 15) { float mv = fin * inv_m; sq[wl][4] = mv; g_pmean[n].y = mv; }
        if (lane == 16) { float mv = sz  * inv_m; sq[wl][5] = mv; g_pmean[n].z = mv; }

        int4 cc = coors[n];
        if (lane == 0) sq[wl][0] = fmaf((float)cc.w, 0.2f, 0.1f);
        if (lane == 1) sq[wl][1] = fmaf((float)cc.z, 0.2f, -39.9f);
        if (lane == 2) sq[wl][2] = fmaf((float)cc.y, 4.0f, -1.0f);
        __syncwarp();

        // accumulate this pillar's moment contributions into registers
        const float* sqw = sq[wl];
        a0 += fin;                              // used only by lanes < 14
        a1 += tail_val(14 + lane, sqw, fm);     // slots 14..45
        if (lane < 19) a2 += tail_val(46 + lane, sqw, fm); // slots 46..64
        __syncwarp();
    }

    // write accumulated slots to shared, then block-reduce + atomic
    {
        float* r = red[wl];
        if (lane < 14) r[lane] = a0;
        r[14 + lane] = a1;
        if (lane < 19) r[46 + lane] = a2;
    }
    __syncthreads();
    if (tid < 65) {
        double acc = 0.0;
#pragma unroll
        for (int w2 = 0; w2 < 8; w2++) acc += (double)red[w2][tid];
        atomicAdd(&g_mom[tid], acc);
    }
}

// ---------------- pass 2: per-block BN fold + fused PFN + maxes; last block resets ----------------
__global__ __launch_bounds__(256, 5) void k_pass2(
    const float4* __restrict__ feat, const int* __restrict__ npts,
    const int4*  __restrict__ coors, float* __restrict__ out,
    const float* __restrict__ pfn_w,
    const float* __restrict__ gamma, const float* __restrict__ beta)
{
    __shared__ __align__(16) float4 sp[8][32];
    __shared__ float  sw[8][32];
    __shared__ __align__(16) float smom[65];
    __shared__ __align__(16) float sA[64 * 4];   // float4 loads -> 16B aligned
    __shared__ __align__(8)  float sG[6 * 64];   // float2 loads -> 8B aligned
    __shared__ __align__(8)  float sT[64];       // float2 loads -> 8B aligned
    const int tid  = threadIdx.x;
    const int lane = tid & 31;
    const int wl   = tid >> 5;
    const int gw   = blockIdx.x * 8 + wl;
    const int nw   = gridDim.x * 8;

    // ---- prologue: BN fold in fp32 (per block, redundant but cheap) ----
    if (tid < 65) smom[tid] = (float)g_mom[tid];
    __syncthreads();
    if (tid < 64) {
        const int c = tid;
        float W[10];
#pragma unroll
        for (int r = 0; r < 10; r++) W[r] = pfn_w[r * 64 + c];
        float A[4] = { W[0]+W[4]+W[7], W[1]+W[5]+W[8], W[2]+W[6]+W[9], W[3] };
        float G[6] = { -(W[0]+W[7]), -(W[1]+W[8]), -(W[2]+W[9]), -W[4], -W[5], -W[6] };

        float S1 = 0.f;
#pragma unroll
        for (int d = 0; d < 4; d++) S1 += smom[10 + d] * A[d];
#pragma unroll
        for (int a = 0; a < 6; a++) S1 += smom[59 + a] * G[a];
        float mean = S1 * (1.0f / NMTOT);

        float E2 = 0.f;
        int pi = 0;
#pragma unroll
        for (int d = 0; d < 4; d++)
#pragma unroll
            for (int e = d; e < 4; e++)
                E2 += (d == e ? 1.f : 2.f) * A[d] * A[e] * smom[pi++];
#pragma unroll
        for (int a = 0; a < 6; a++)
#pragma unroll
            for (int d = 0; d < 4; d++)
                E2 += 2.f * G[a] * A[d] * smom[14 + a * 4 + d];
        int qi = 38;
#pragma unroll
        for (int a = 0; a < 6; a++)
#pragma unroll
            for (int b = a; b < 6; b++)
                E2 += (a == b ? 1.f : 2.f) * G[a] * G[b] * smom[qi++];
        E2 *= (1.0f / NMTOT);

        float var = E2 - mean * mean;
        float s = gamma[c] * rsqrtf(var + 1e-3f);
        float t = beta[c] - mean * s;
#pragma unroll
        for (int d = 0; d < 4; d++) sA[c * 4 + d] = A[d] * s;
#pragma unroll
        for (int a = 0; a < 6; a++) sG[a * 64 + c] = G[a] * s;
        sT[c] = t;
    }
    __syncthreads();

    // coefficients for channel pair (2*lane, 2*lane+1)
    float4 Aa = *(const float4*)&sA[(2 * lane) * 4];
    float4 Ab = *(const float4*)&sA[(2 * lane + 1) * 4];
    float2 Gv[6];
#pragma unroll
    for (int a = 0; a < 6; a++) Gv[a] = ((const float2*)(sG + 64 * a))[lane];
    float2 tv = ((const float2*)sT)[lane];
    const float tp0 = fmaxf(tv.x, 0.01f * tv.x);
    const float tp1 = fmaxf(tv.y, 0.01f * tv.y);

    for (int n = gw; n < NPIL; n += nw) {
        float4 f  = feat[n * MPTS + lane];
        float  wv = g_w[n * MPTS + lane];
        const int m = npts[n];
        int4 cc = coors[n];
        float4 pmv = g_pmean[n];
        float2 wmm = g_wmm[n];
        sp[wl][lane] = f;
        sw[wl][lane] = wv;
        __syncwarp();

        float k0 = tv.x, k1 = tv.y;
        {
            float q0 = fmaf((float)cc.w, 0.2f, 0.1f);
            float q1 = fmaf((float)cc.z, 0.2f, -39.9f);
            float q2 = fmaf((float)cc.y, 4.0f, -1.0f);
            k0 = fmaf(q0, Gv[0].x, fmaf(q1, Gv[1].x, fmaf(q2, Gv[2].x,
                 fmaf(pmv.x, Gv[3].x, fmaf(pmv.y, Gv[4].x, fmaf(pmv.z, Gv[5].x, k0))))));
            k1 = fmaf(q0, Gv[0].y, fmaf(q1, Gv[1].y, fmaf(q2, Gv[2].y,
                 fmaf(pmv.x, Gv[3].y, fmaf(pmv.y, Gv[4].y, fmaf(pmv.z, Gv[5].y, k1))))));
        }

        float fm0, fm1, fa0, fa1;
        if (m < MPTS) {                  // masked rows contribute x = t_c
            fm0 = tp0; fm1 = tp1;
            fa0 = (tp0 >= 0.f) ? tp0 * wmm.x : tp0 * wmm.y;
            fa1 = (tp1 >= 0.f) ? tp1 * wmm.x : tp1 * wmm.y;
        } else {
            fm0 = fm1 = fa0 = fa1 = -FLT_MAX;
        }

#pragma unroll 4
        for (int i = 0; i < m; i++) {
            float4 p = sp[wl][i];
            float wi = sw[wl][i];
            float r0 = fmaf(p.x, Aa.x, fmaf(p.y, Aa.y,
                       fmaf(p.z, Aa.z, fmaf(p.w, Aa.w, k0))));
            float u0 = fmaxf(r0, 0.01f * r0);
            fm0 = fmaxf(fm0, u0);
            fa0 = fmaxf(fa0, wi * u0);
            float r1 = fmaf(p.x, Ab.x, fmaf(p.y, Ab.y,
                       fmaf(p.z, Ab.z, fmaf(p.w, Ab.w, k1))));
            float u1 = fmaxf(r1, 0.01f * r1);
            fm1 = fmaxf(fm1, u1);
            fa1 = fmaxf(fa1, wi * u1);
        }
        ((float2*)(out + n * 64))[lane] =
            make_float2(0.5f * (fa0 + fm0), 0.5f * (fa1 + fm1));
        __syncwarp();
    }

    // ---- ticket: last finishing block resets g_mom for the next replay ----
    __syncthreads();
    if (tid == 0) {
        unsigned t = atomicAdd(&g_ctr2, 1u);
        if (t == gridDim.x - 1) {
            for (int i = 0; i < 65; i++) g_mom[i] = 0.0;
            g_ctr2 = 0;
        }
    }
}

// ---------------- launch ----------------
extern "C" void kernel_launch(void* const* d_in, const int* in_sizes, int n_in,
                              void* d_out, int out_size)
{
    const float4* feat  = (const float4*)d_in[0];
    const int*    npts  = (const int*)  d_in[1];
    const int4*   coors = (const int4*) d_in[2];
    const float*  pfn_w = (const float*)d_in[3];
    const float*  gamma = (const float*)d_in[4];
    const float*  beta  = (const float*)d_in[5];
    const float*  wq    = (const float*)d_in[6];
    const float*  wk    = (const float*)d_in[7];
    const float*  wv    = (const float*)d_in[8];
    const float*  wo    = (const float*)d_in[9];
    const float*  bq    = (const float*)d_in[10];
    const float*  bk    = (const float*)d_in[11];
    const float*  bv    = (const float*)d_in[12];
    const float*  bo    = (const float*)d_in[13];
    float* out = (float*)d_out;

    k_pass1<<<HALFP / 8, 256>>>(feat, npts, coors, wq, wk, wv, wo,
                                bq, bk, bv, bo);
    k_pass2<<<740, 256>>>(feat, npts, coors, out, pfn_w, gamma, beta);
}

// round 12
// speedup vs baseline: 1.0640x; 1.0355x over previous
#include <cuda_runtime.h>
#include <cfloat>
#include <math.h>

#define NPIL 30000
#define MPTS 32
#define NBLK 592
#define PPB  51                       // ceil(30000/592); 592*51 = 30192
#define NMTOT (30000.0f * 32.0f)
#define LOG2E 1.4426950408889634f

// ---------------- globals (zero-init; counters reset by last block) ----------------
__device__ double   g_mom[65];
__device__ unsigned g_arrive;
__device__ unsigned g_done;

// QQ triangular index tables (l-38 -> (a,b))
__constant__ signed char d_qa[21] = {0,0,0,0,0,0,1,1,1,1,1,2,2,2,2,3,3,3,4,4,5};
__constant__ signed char d_qb[21] = {0,1,2,3,4,5,1,2,3,4,5,2,3,4,5,3,4,5,4,5,5};

__device__ __forceinline__ float ex2f(float x) {
    float y; asm("ex2.approx.f32 %0, %1;" : "=f"(y) : "f"(x)); return y;
}
__device__ __forceinline__ float wredsum(float v) {
#pragma unroll
    for (int o = 16; o; o >>= 1) v += __shfl_xor_sync(0xffffffffu, v, o);
    return v;
}
__device__ __forceinline__ float wredmax(float v) {
#pragma unroll
    for (int o = 16; o; o >>= 1) v = fmaxf(v, __shfl_xor_sync(0xffffffffu, v, o));
    return v;
}
__device__ __forceinline__ float wredmin(float v) {
#pragma unroll
    for (int o = 16; o; o >>= 1) v = fminf(v, __shfl_xor_sync(0xffffffffu, v, o));
    return v;
}

// moment-tail: value for red slot l (14..64); sqw[0..5]=q6, sqw[6..9]=Sv
__device__ __forceinline__ float tail_val(int l, const float* sqw, float fm) {
    if (l < 38) { int u = l - 14; return sqw[u >> 2] * sqw[6 + (u & 3)]; }
    if (l < 59) { int u = l - 38; return fm * sqw[(int)d_qa[u]] * sqw[(int)d_qb[u]]; }
    return fm * sqw[l - 59];
}

// ---------------- single persistent kernel ----------------
__global__ __launch_bounds__(256, 4) void k_fused(
    const float4* __restrict__ feat, const int* __restrict__ npts,
    const int4*  __restrict__ coors, float* __restrict__ out,
    const float* __restrict__ wq, const float* __restrict__ wk,
    const float* __restrict__ wv, const float* __restrict__ wo,
    const float* __restrict__ bq, const float* __restrict__ bk,
    const float* __restrict__ bv, const float* __restrict__ bo,
    const float* __restrict__ pfn_w,
    const float* __restrict__ gamma, const float* __restrict__ beta)
{
    __shared__ __align__(16) float4 s_feat[PPB][32];   // 26112 B
    __shared__ float  s_w[PPB][32];                    //  6528 B
    __shared__ float  s_cst[PPB][10];                  //  2040 B  q6[6],{Sv->wmmx,wmmy,fm},Sv3
    __shared__ __align__(16) float u_kvs[8][32][8];    //  8192 B  (phase A temp | fold arrays)
    __shared__ float  red[8][65];                      //  2080 B
    __shared__ float  swt[48];                         //   192 B

    const int tid  = threadIdx.x;
    const int wl   = tid >> 5;
    const int lane = tid & 31;
    const int base = blockIdx.x * PPB;
    const int P    = min(PPB, NPIL - base) > 0 ? min(PPB, NPIL - base) : 0;

    {   // stage small weights
        int t = tid;
        if      (t <  9) swt[t] = wq[t];
        else if (t < 18) swt[t] = wk[t - 9];
        else if (t < 27) swt[t] = wv[t - 18];
        else if (t < 36) swt[t] = wo[t - 27];
        else if (t < 39) swt[t] = bq[t - 36];
        else if (t < 42) swt[t] = bk[t - 39];
        else if (t < 45) swt[t] = bv[t - 42];
        else if (t < 48) swt[t] = bo[t - 45];
    }
    __syncthreads();

    // ================= PHASE A: attention + moments, park data in smem =================
    float a0 = 0.f, a1 = 0.f, a2 = 0.f;

#pragma unroll 1
    for (int slot = wl; slot < P; slot += 8) {
        const int n = base + slot;
        float4 f = feat[n * MPTS + lane];
        const float x = f.x, y = f.y, z = f.z, I = f.w;
        s_feat[slot][lane] = f;

        float q0 = fmaf(x, swt[0], fmaf(y, swt[3], fmaf(z, swt[6], swt[36])));
        float q1 = fmaf(x, swt[1], fmaf(y, swt[4], fmaf(z, swt[7], swt[37])));
        float q2 = fmaf(x, swt[2], fmaf(y, swt[5], fmaf(z, swt[8], swt[38])));
        float k0 = fmaf(x, swt[ 9], fmaf(y, swt[12], fmaf(z, swt[15], swt[39])));
        float k1 = fmaf(x, swt[10], fmaf(y, swt[13], fmaf(z, swt[16], swt[40])));
        float k2 = fmaf(x, swt[11], fmaf(y, swt[14], fmaf(z, swt[17], swt[41])));
        float v0 = fmaf(x, swt[18], fmaf(y, swt[21], fmaf(z, swt[24], swt[42])));
        float v1 = fmaf(x, swt[19], fmaf(y, swt[22], fmaf(z, swt[25], swt[43])));
        float v2 = fmaf(x, swt[20], fmaf(y, swt[23], fmaf(z, swt[26], swt[44])));

        float* kp = u_kvs[wl][lane];
        *(float4*)kp       = make_float4(k0 * LOG2E, k1 * LOG2E, k2 * LOG2E, v0);
        *(float2*)(kp + 4) = make_float2(v1, v2);
        __syncwarp();

        float n0a = 0.f, n1a = 0.f, n2a = 0.f, d0 = 0.f, d1 = 0.f, d2 = 0.f;
#pragma unroll
        for (int j = 0; j < 32; j++) {
            const float* kj = u_kvs[wl][j];
            float4 a = *(const float4*)kj;
            float2 b = *(const float2*)(kj + 4);
            float e0 = ex2f(q0 * a.x);
            float e1 = ex2f(q1 * a.y);
            float e2 = ex2f(q2 * a.z);
            n0a = fmaf(e0, a.w, n0a); d0 += e0;
            n1a = fmaf(e1, b.x, n1a); d1 += e1;
            n2a = fmaf(e2, b.y, n2a); d2 += e2;
        }
        float o0 = __fdividef(n0a, d0);
        float o1 = __fdividef(n1a, d1);
        float o2 = __fdividef(n2a, d2);

        float b0 = fmaf(o0, swt[27], fmaf(o1, swt[30], fmaf(o2, swt[33], swt[45])));
        float b1 = fmaf(o0, swt[28], fmaf(o1, swt[31], fmaf(o2, swt[34], swt[46])));
        float b2 = fmaf(o0, swt[29], fmaf(o1, swt[32], fmaf(o2, swt[35], swt[47])));
        float matt = fmaxf(b0, fmaxf(b1, b2));

        float ssum = wredsum(matt);
        float wgt = matt / ssum;
        s_w[slot][lane] = wgt;

        const int m = npts[n];
        const float fm = (float)m;
        const float inv_m = 1.0f / fm;
        const bool act = lane < m;

        float wmx = wredmax(act ? -FLT_MAX : wgt);
        float wmn = wredmin(act ?  FLT_MAX : wgt);

        // 16-value reduce-scatter: V[0..13] masked moments, V[14]=x, V[15]=y
        float px = act ? x : 0.f, py = act ? y : 0.f;
        float pz = act ? z : 0.f, pI = act ? I : 0.f;
        float V[16] = { px*px, px*py, px*pz, px*pI, py*py, py*pz, py*pI,
                        pz*pz, pz*pI, pI*pI, px, py, pz, pI, x, y };
#pragma unroll
        for (int t = 0; t < 16; t++)
            V[t] += __shfl_xor_sync(0xffffffffu, V[t], 16);
        float W8[8];
#pragma unroll
        for (int t = 0; t < 8; t++) {
            bool hi = (lane & 8);
            float snd = hi ? V[t] : V[t + 8];
            float kp2 = hi ? V[t + 8] : V[t];
            W8[t] = kp2 + __shfl_xor_sync(0xffffffffu, snd, 8);
        }
        float W4[4];
#pragma unroll
        for (int t = 0; t < 4; t++) {
            bool hi = (lane & 4);
            float snd = hi ? W8[t] : W8[t + 4];
            float kp2 = hi ? W8[t + 4] : W8[t];
            W4[t] = kp2 + __shfl_xor_sync(0xffffffffu, snd, 4);
        }
        float W2[2];
#pragma unroll
        for (int t = 0; t < 2; t++) {
            bool hi = (lane & 2);
            float snd = hi ? W4[t] : W4[t + 2];
            float kp2 = hi ? W4[t + 2] : W4[t];
            W2[t] = kp2 + __shfl_xor_sync(0xffffffffu, snd, 2);
        }
        float fin;
        {
            bool hi = (lane & 1);
            float snd = hi ? W2[0] : W2[1];
            float kp2 = hi ? W2[1] : W2[0];
            fin = kp2 + __shfl_xor_sync(0xffffffffu, snd, 1);
        }
        float sz = wredsum(z);

        // scatter per-pillar scalars
        if (lane >= 26 && lane < 30) s_cst[slot][lane - 20] = fin;        // Sv -> [6..9]
        if (lane == 14) s_cst[slot][3] = fin * inv_m;                     // mx
        if (lane == 15) s_cst[slot][4] = fin * inv_m;                     // my
        if (lane == 16) s_cst[slot][5] = sz  * inv_m;                     // mz
        int4 cc = coors[n];
        if (lane == 0) s_cst[slot][0] = fmaf((float)cc.w, 0.2f, 0.1f);
        if (lane == 1) s_cst[slot][1] = fmaf((float)cc.z, 0.2f, -39.9f);
        if (lane == 2) s_cst[slot][2] = fmaf((float)cc.y, 4.0f, -1.0f);
        __syncwarp();

        const float* sqw = s_cst[slot];
        a0 += fin;                                   // lanes <14 meaningful
        a1 += tail_val(14 + lane, sqw, fm);          // slots 14..45
        if (lane < 19) a2 += tail_val(46 + lane, sqw, fm);  // 46..64
        __syncwarp();

        // overwrite Sv[0..2] with phase-B constants (Sv no longer needed)
        if (lane == 0) { s_cst[slot][6] = wmx; s_cst[slot][7] = wmn; s_cst[slot][8] = fm; }
        __syncwarp();
    }

    // block reduce + atomic
    {
        float* r = red[wl];
        if (lane < 14) r[lane] = a0;
        r[14 + lane] = a1;
        if (lane < 19) r[46 + lane] = a2;
    }
    __syncthreads();
    if (tid < 65) {
        double acc = 0.0;
#pragma unroll
        for (int w2 = 0; w2 < 8; w2++) acc += (double)red[w2][tid];
        atomicAdd(&g_mom[tid], acc);
        __threadfence();
    }
    __syncthreads();

    // ================= DEVICE BARRIER =================
    if (tid == 0) {
        __threadfence();
        atomicAdd(&g_arrive, 1u);
        while (atomicAdd(&g_arrive, 0u) < NBLK) __nanosleep(200);
    }
    __syncthreads();
    __threadfence();

    // ================= per-block BN fold (fp32), arrays overlay u_kvs =================
    float* smom = &u_kvs[0][0][0];   // 65
    float* sA   = smom + 80;         // 256, 16B aligned
    float* sG   = sA + 256;          // 384, 8B aligned
    float* sT   = sG + 384;          // 64,  8B aligned

    if (tid < 65) smom[tid] = (float)((volatile double*)g_mom)[tid];
    __syncthreads();
    if (tid < 64) {
        const int c = tid;
        float W[10];
#pragma unroll
        for (int r = 0; r < 10; r++) W[r] = pfn_w[r * 64 + c];
        float A[4] = { W[0]+W[4]+W[7], W[1]+W[5]+W[8], W[2]+W[6]+W[9], W[3] };
        float G[6] = { -(W[0]+W[7]), -(W[1]+W[8]), -(W[2]+W[9]), -W[4], -W[5], -W[6] };

        float S1 = 0.f;
#pragma unroll
        for (int d = 0; d < 4; d++) S1 += smom[10 + d] * A[d];
#pragma unroll
        for (int a = 0; a < 6; a++) S1 += smom[59 + a] * G[a];
        float mean = S1 * (1.0f / NMTOT);

        float E2 = 0.f;
        int pi = 0;
#pragma unroll
        for (int d = 0; d < 4; d++)
#pragma unroll
            for (int e = d; e < 4; e++)
                E2 += (d == e ? 1.f : 2.f) * A[d] * A[e] * smom[pi++];
#pragma unroll
        for (int a = 0; a < 6; a++)
#pragma unroll
            for (int d = 0; d < 4; d++)
                E2 += 2.f * G[a] * A[d] * smom[14 + a * 4 + d];
        int qi = 38;
#pragma unroll
        for (int a = 0; a < 6; a++)
#pragma unroll
            for (int b = a; b < 6; b++)
                E2 += (a == b ? 1.f : 2.f) * G[a] * G[b] * smom[qi++];
        E2 *= (1.0f / NMTOT);

        float var = E2 - mean * mean;
        float s = gamma[c] * rsqrtf(var + 1e-3f);
        float t = beta[c] - mean * s;
#pragma unroll
        for (int d = 0; d < 4; d++) sA[c * 4 + d] = A[d] * s;
#pragma unroll
        for (int a = 0; a < 6; a++) sG[a * 64 + c] = G[a] * s;
        sT[c] = t;
    }
    __syncthreads();

    // ================= PHASE B: pure-smem PFN + maxes =================
    float4 Aa = *(const float4*)&sA[(2 * lane) * 4];
    float4 Ab = *(const float4*)&sA[(2 * lane + 1) * 4];
    float2 Gv[6];
#pragma unroll
    for (int a = 0; a < 6; a++) Gv[a] = ((const float2*)(sG + 64 * a))[lane];
    float2 tv = ((const float2*)sT)[lane];
    const float tp0 = fmaxf(tv.x, 0.01f * tv.x);
    const float tp1 = fmaxf(tv.y, 0.01f * tv.y);

#pragma unroll 1
    for (int slot = wl; slot < P; slot += 8) {
        const int n = base + slot;
        const float* cst = s_cst[slot];
        const float fm_s = cst[8];
        const int   m    = (int)fm_s;
        const float wmmx = cst[6], wmmy = cst[7];

        float k0 = tv.x, k1 = tv.y;
#pragma unroll
        for (int a = 0; a < 6; a++) {
            float qa = cst[a];
            k0 = fmaf(qa, Gv[a].x, k0);
            k1 = fmaf(qa, Gv[a].y, k1);
        }

        float fm0, fm1, fa0, fa1;
        if (m < MPTS) {
            fm0 = tp0; fm1 = tp1;
            fa0 = (tp0 >= 0.f) ? tp0 * wmmx : tp0 * wmmy;
            fa1 = (tp1 >= 0.f) ? tp1 * wmmx : tp1 * wmmy;
        } else {
            fm0 = fm1 = fa0 = fa1 = -FLT_MAX;
        }

#pragma unroll 4
        for (int i = 0; i < m; i++) {
            float4 p = s_feat[slot][i];
            float wi = s_w[slot][i];
            float r0 = fmaf(p.x, Aa.x, fmaf(p.y, Aa.y,
                       fmaf(p.z, Aa.z, fmaf(p.w, Aa.w, k0))));
            float u0 = fmaxf(r0, 0.01f * r0);
            fm0 = fmaxf(fm0, u0);
            fa0 = fmaxf(fa0, wi * u0);
            float r1 = fmaf(p.x, Ab.x, fmaf(p.y, Ab.y,
                       fmaf(p.z, Ab.z, fmaf(p.w, Ab.w, k1))));
            float u1 = fmaxf(r1, 0.01f * r1);
            fm1 = fmaxf(fm1, u1);
            fa1 = fmaxf(fa1, wi * u1);
        }
        ((float2*)(out + n * 64))[lane] =
            make_float2(0.5f * (fa0 + fm0), 0.5f * (fa1 + fm1));
    }

    // ================= last block resets counters for next replay =================
    __syncthreads();
    if (tid == 0) {
        __threadfence();
        unsigned d = atomicAdd(&g_done, 1u);
        if (d == NBLK - 1) {
            for (int i = 0; i < 65; i++) g_mom[i] = 0.0;
            g_arrive = 0u;
            g_done = 0u;
            __threadfence();
        }
    }
}

// ---------------- launch ----------------
extern "C" void kernel_launch(void* const* d_in, const int* in_sizes, int n_in,
                              void* d_out, int out_size)
{
    const float4* feat  = (const float4*)d_in[0];
    const int*    npts  = (const int*)  d_in[1];
    const int4*   coors = (const int4*) d_in[2];
    const float*  pfn_w = (const float*)d_in[3];
    const float*  gamma = (const float*)d_in[4];
    const float*  beta  = (const float*)d_in[5];
    const float*  wq    = (const float*)d_in[6];
    const float*  wk    = (const float*)d_in[7];
    const float*  wv    = (const float*)d_in[8];
    const float*  wo    = (const float*)d_in[9];
    const float*  bq    = (const float*)d_in[10];
    const float*  bk    = (const float*)d_in[11];
    const float*  bv    = (const float*)d_in[12];
    const float*  bo    = (const float*)d_in[13];
    float* out = (float*)d_out;

    k_fused<<<NBLK, 256>>>(feat, npts, coors, out, wq, wk, wv, wo,
                           bq, bk, bv, bo, pfn_w, gamma, beta);
}